// round 5
// baseline (speedup 1.0000x reference)
#include <cuda_runtime.h>
#include <cstdint>
#include <cfloat>

// Problem constants (fixed by the dataset)
constexpr int Bv  = 16;      // batch
constexpr int Nv  = 16384;   // pixels
constexpr int Dv  = 64;      // embed dim
constexpr int Kv  = 64;      // templates
constexpr int D4v = Dv / 4;  // float4 chunks per vector (16)
constexpr int TP  = 17;      // template tile pitch in float4 (conflict-free)
constexpr int XP  = 20;      // transposed-x row pitch in floats (16B-aligned rows)
constexpr float EPS = 1e-3f; // near-tie margin (>> fp32 dist error ~1e-5)

// ---- packed f32x2 helpers (sm_103a; PTX-only ops) ----
__device__ __forceinline__ unsigned long long f2_fma(unsigned long long a,
                                                     unsigned long long b,
                                                     unsigned long long c) {
    unsigned long long d;
    asm("fma.rn.f32x2 %0, %1, %2, %3;" : "=l"(d) : "l"(a), "l"(b), "l"(c));
    return d;
}
__device__ __forceinline__ unsigned long long f2_add(unsigned long long a,
                                                     unsigned long long b) {
    unsigned long long d;
    asm("add.rn.f32x2 %0, %1, %2;" : "=l"(d) : "l"(a), "l"(b));
    return d;
}
__device__ __forceinline__ unsigned long long f2_splat(float f) {
    unsigned long long r; unsigned u = __float_as_uint(f);
    asm("mov.b64 %0, {%1, %1};" : "=l"(r) : "r"(u));
    return r;
}
__device__ __forceinline__ void f2_unpack(unsigned long long p, float& lo, float& hi) {
    unsigned a, b;
    asm("mov.b64 {%0, %1}, %2;" : "=r"(a), "=r"(b) : "l"(p));
    lo = __uint_as_float(a); hi = __uint_as_float(b);
}

__global__ __launch_bounds__(64, 8)
void osc_kernel(const float4* __restrict__ xg,     // frame_embeddings [B,N,D] f32
                const float4* __restrict__ tg,     // templates        [K,N,D] f32
                const int*    __restrict__ tcls,   // template_classes [K] int32
                float* __restrict__ out)
{
    __shared__ __align__(16) float4 ts[Kv * TP];     // template tile (row-major)
    __shared__ __align__(16) float  xs_t[Dv * XP];   // x transposed [d][b]
    __shared__ __align__(16) float  x2s[Bv];         // ||x_b||^2
    __shared__ float  ds[Bv * 65];                   // dist matrix [b][k], padded
    __shared__ float  clsf[Kv];
    __shared__ float  pv[32];
    __shared__ int    pki[32];
    __shared__ float  bestvs[Bv];
    __shared__ int    bestks[Bv];
    __shared__ int    cnt[Bv];
    __shared__ unsigned long long refined[Bv];

    const int n   = blockIdx.x;
    const int tid = threadIdx.x;
    const int k   = tid;                 // this thread's template

    // ---- stage template tile (coalesced 256B rows) ----
#pragma unroll
    for (int i = 0; i < 16; ++i) {
        int idx = tid + i * 64;
        int kk  = idx >> 4;
        int d4  = idx & 15;
        ts[kk * TP + d4] = tg[((size_t)kk * Nv + n) * D4v + d4];
    }
    // ---- stage x transposed: [d][b] with pitch XP (coalesced reads) ----
#pragma unroll
    for (int i = 0; i < 4; ++i) {
        int idx = tid + i * 64;
        int b   = idx >> 4;
        int d4  = idx & 15;
        float4 v = xg[((size_t)b * Nv + n) * D4v + d4];
        xs_t[(4 * d4 + 0) * XP + b] = v.x;
        xs_t[(4 * d4 + 1) * XP + b] = v.y;
        xs_t[(4 * d4 + 2) * XP + b] = v.z;
        xs_t[(4 * d4 + 3) * XP + b] = v.w;
    }
    clsf[tid] = (float)tcls[tid];
    if (tid < Bv) {
        cnt[tid]     = 0;
        refined[tid] = 0xFFFFFFFFFFFFFFFFULL;
    }
    __syncthreads();

    // ---- ||x_b||^2 (threads 0..15, column scan) ----
    if (tid < Bv) {
        float s = 0.f;
#pragma unroll
        for (int d = 0; d < Dv; ++d) {
            float v = xs_t[d * XP + tid];
            s = fmaf(v, v, s);
        }
        x2s[tid] = s;
    }
    __syncthreads();

    // ---- main loop: thread k computes xt dot for all 16 b (packed f32x2) ----
    unsigned long long acc2[8];
#pragma unroll
    for (int i = 0; i < 8; ++i) acc2[i] = 0ULL;   // bits 0 == (0.f, 0.f)
    float t2 = 0.f;

    const float4* tsrow = &ts[k * TP];
#pragma unroll
    for (int d4 = 0; d4 < D4v; ++d4) {
        const float4 tv = tsrow[d4];              // conflict-free LDS.128
        const float tvj[4] = {tv.x, tv.y, tv.z, tv.w};
#pragma unroll
        for (int j = 0; j < 4; ++j) {
            const float tf = tvj[j];
            t2 = fmaf(tf, tf, t2);
            const unsigned long long tt = f2_splat(tf);
            const ulonglong2* xr = reinterpret_cast<const ulonglong2*>(
                &xs_t[(4 * d4 + j) * XP]);        // broadcast LDS.128 x4
            const ulonglong2 p01 = xr[0];
            const ulonglong2 p23 = xr[1];
            const ulonglong2 p45 = xr[2];
            const ulonglong2 p67 = xr[3];
            acc2[0] = f2_fma(p01.x, tt, acc2[0]);
            acc2[1] = f2_fma(p01.y, tt, acc2[1]);
            acc2[2] = f2_fma(p23.x, tt, acc2[2]);
            acc2[3] = f2_fma(p23.y, tt, acc2[3]);
            acc2[4] = f2_fma(p45.x, tt, acc2[4]);
            acc2[5] = f2_fma(p45.y, tt, acc2[5]);
            acc2[6] = f2_fma(p67.x, tt, acc2[6]);
            acc2[7] = f2_fma(p67.y, tt, acc2[7]);
        }
    }

    // ---- distances: d = x2 + t2 - 2*xt  (packed), keep regs + write smem ----
    const unsigned long long t22 = f2_splat(t2);
    const unsigned long long m2  = f2_splat(-2.0f);
    const unsigned long long* x2p = reinterpret_cast<const unsigned long long*>(x2s);
    float df[16];
#pragma unroll
    for (int i = 0; i < 8; ++i) {
        const unsigned long long s  = f2_add(x2p[i], t22);
        const unsigned long long dd = f2_fma(acc2[i], m2, s);
        f2_unpack(dd, df[2 * i], df[2 * i + 1]);
        ds[(2 * i)     * 65 + k] = df[2 * i];
        ds[(2 * i + 1) * 65 + k] = df[2 * i + 1];
    }
    __syncthreads();

    // ---- min+argmin per b: 32 threads scan half the k range each ----
    if (tid < 32) {
        const int b = tid & 15;
        const int h = tid >> 4;
        const float* row = &ds[b * 65 + h * 32];
        float best = FLT_MAX;
        int   bk   = h * 32;
#pragma unroll
        for (int kk = 0; kk < 32; ++kk) {
            const float v = row[kk];
            if (v < best) { best = v; bk = h * 32 + kk; }  // strict < => first occurrence
        }
        pv[tid]  = best;
        pki[tid] = bk;
    }
    __syncthreads();
    if (tid < Bv) {
        float v0 = pv[tid];      int k0 = pki[tid];
        float v1 = pv[tid + 16]; int k1 = pki[tid + 16];
        // tie -> lower half (lower k)
        if (v1 < v0) { v0 = v1; k0 = k1; }
        bestvs[tid] = v0;
        bestks[tid] = k0;
    }
    __syncthreads();

    // ---- near-tie candidate count per b ----
#pragma unroll
    for (int b = 0; b < Bv; ++b) {
        if (df[b] <= bestvs[b] + EPS) atomicAdd(&cnt[b], 1);
    }
    __syncthreads();

    // ---- RARE: exact fp64 refinement for contested b ----
#pragma unroll
    for (int b = 0; b < Bv; ++b) {
        if (cnt[b] < 2) continue;
        if (df[b] > bestvs[b] + EPS) continue;
        double dd = 0.0;
        for (int d4 = 0; d4 < D4v; ++d4) {
            const float4 tv = tsrow[d4];
            const float tvj[4] = {tv.x, tv.y, tv.z, tv.w};
            for (int j = 0; j < 4; ++j) {
                const double e = (double)xs_t[(4 * d4 + j) * XP + b] - (double)tvj[j];
                dd = fma(e, e, dd);
            }
        }
        const float dfx = (float)dd;              // exact -> fp32
        const unsigned long long key =
            ((unsigned long long)__float_as_uint(dfx) << 6) |
            (unsigned long long)k;
        atomicMin(&refined[b], key);
    }
    __syncthreads();

    // ---- outputs ----
    if (tid < Bv) {
        float bestv;
        int   bestk;
        if (cnt[tid] >= 2) {
            const unsigned long long key = refined[tid];
            bestk = (int)(key & 63ULL);
            bestv = __uint_as_float((unsigned int)(key >> 6));
        } else {
            bestv = bestvs[tid];
            bestk = bestks[tid];
        }
        const size_t BN = (size_t)Bv * Nv;
        const size_t o  = (size_t)tid * Nv + n;
        out[o]           = (bestv <= 0.5f) ? 1.0f : 0.0f;  // mask @ 0.5
        out[BN + o]      = (bestv <= 1.0f) ? 1.0f : 0.0f;  // mask @ 1.0
        out[2 * BN + o]  = bestv;                          // min_dists
        out[3 * BN + o]  = clsf[bestk];                    // pred_classes
    }
}

extern "C" void kernel_launch(void* const* d_in, const int* in_sizes, int n_in,
                              void* d_out, int out_size)
{
    const float4* frame = (const float4*)d_in[0];   // [16,16384,64] f32
    const float4* tmpl  = (const float4*)d_in[1];   // [64,16384,64] f32
    const int*    tcls  = (const int*)d_in[2];      // [64] int32
    float*        out   = (float*)d_out;

    osc_kernel<<<Nv, 64>>>(frame, tmpl, tcls, out);
}

// round 6
// speedup vs baseline: 1.0002x; 1.0002x over previous
#include <cuda_runtime.h>
#include <cstdint>
#include <cfloat>

// Problem constants (fixed by the dataset)
constexpr int Bv  = 16;      // batch
constexpr int Nv  = 16384;   // pixels
constexpr int Dv  = 64;      // embed dim
constexpr int Kv  = 64;      // templates
constexpr int D4v = Dv / 4;  // float4 chunks per vector (16)
constexpr int TP  = 17;      // template tile pitch in float4 (conflict-free)
constexpr float EPS = 1e-3f; // near-tie margin (>> fp32 dist error ~1e-5)

using ull = unsigned long long;

// ---- packed f32x2 helpers (sm_103a; PTX-only ops; per-lane rounding == fmaf) ----
__device__ __forceinline__ ull f2_fma(ull a, ull b, ull c) {
    ull d;
    asm("fma.rn.f32x2 %0, %1, %2, %3;" : "=l"(d) : "l"(a), "l"(b), "l"(c));
    return d;
}
__device__ __forceinline__ ull f2_add(ull a, ull b) {
    ull d;
    asm("add.rn.f32x2 %0, %1, %2;" : "=l"(d) : "l"(a), "l"(b));
    return d;
}
__device__ __forceinline__ ull f2_splat(float f) {
    ull r; unsigned u = __float_as_uint(f);
    asm("mov.b64 %0, {%1, %1};" : "=l"(r) : "r"(u));
    return r;
}
__device__ __forceinline__ void f2_unpack(ull p, float& lo, float& hi) {
    unsigned a, b;
    asm("mov.b64 {%0, %1}, %2;" : "=r"(a), "=r"(b) : "l"(p));
    lo = __uint_as_float(a); hi = __uint_as_float(b);
}

// b <-> (slot, half) mapping for the pair-packed x layout.
// pair slot s = (b&3) + 4*((b>>3)&1), half h = (b>>2)&1
// i.e. slot c   holds (x[c],    x[c+4])   -> thread's pair i=0
//      slot c+4 holds (x[c+8],  x[c+12])  -> thread's pair i=1
__device__ __forceinline__ int xslot_f(int b) { return (b & 3) + 4 * ((b >> 3) & 1); }
__device__ __forceinline__ int xhalf_f(int b) { return (b >> 2) & 1; }

__global__ __launch_bounds__(64, 8)
void osc_kernel(const float4* __restrict__ xg,     // frame_embeddings [B,N,D] f32
                const float4* __restrict__ tg,     // templates        [K,N,D] f32
                const int*    __restrict__ tcls,   // template_classes [K] int32
                float* __restrict__ out)
{
    __shared__ __align__(16) float4 ts[Kv * TP];   // template tile (17.4 KB)
    __shared__ __align__(16) float  xs2[Dv * 16];  // x transposed, pair-packed [d][16] (4 KB)
    __shared__ __align__(8)  float  x2arr[16];     // ||x_b||^2 in pair-packed order
    __shared__ float  t2s[Kv];
    __shared__ float  clsf[Kv];
    __shared__ float  ds[Bv * 65];                 // dist matrix [b][k], padded
    __shared__ float  pv[32];
    __shared__ int    pki[32];
    __shared__ float  bestvs[Bv];
    __shared__ int    bestks[Bv];
    __shared__ int    cnt[Bv];
    __shared__ ull    refined[Bv];

    const int n   = blockIdx.x;
    const int tid = threadIdx.x;

    // ---- stage template tile (coalesced 256B rows) ----
#pragma unroll
    for (int i = 0; i < 16; ++i) {
        int idx = tid + i * 64;
        int kk  = idx >> 4;
        int d4  = idx & 15;
        ts[kk * TP + d4] = tg[((size_t)kk * Nv + n) * D4v + d4];
    }
    // ---- stage x transposed + pair-packed: xs2[d][slot*2+half] ----
#pragma unroll
    for (int i = 0; i < 4; ++i) {
        int idx = tid + i * 64;
        int b   = idx >> 4;
        int d4  = idx & 15;
        float4 v = xg[((size_t)b * Nv + n) * D4v + d4];
        int base = xslot_f(b) * 2 + xhalf_f(b);
        xs2[(4 * d4 + 0) * 16 + base] = v.x;
        xs2[(4 * d4 + 1) * 16 + base] = v.y;
        xs2[(4 * d4 + 2) * 16 + base] = v.z;
        xs2[(4 * d4 + 3) * 16 + base] = v.w;
    }
    clsf[tid] = (float)tcls[tid];
    if (tid < Bv) {
        cnt[tid]     = 0;
        refined[tid] = 0xFFFFFFFFFFFFFFFFULL;
    }
    __syncthreads();

    // ---- norms: t2 per template row (fp32), x2 per b (fp32) ----
    {
        float s0 = 0.f, s1 = 0.f, s2 = 0.f, s3 = 0.f;
#pragma unroll
        for (int d4 = 0; d4 < D4v; ++d4) {
            float4 v = ts[tid * TP + d4];
            s0 = fmaf(v.x, v.x, s0); s1 = fmaf(v.y, v.y, s1);
            s2 = fmaf(v.z, v.z, s2); s3 = fmaf(v.w, v.w, s3);
        }
        t2s[tid] = (s0 + s1) + (s2 + s3);
    }
    if (tid < Bv) {
        const int addr = xslot_f(tid) * 2 + xhalf_f(tid);
        float s = 0.f;
#pragma unroll
        for (int d = 0; d < Dv; ++d) {
            float v = xs2[d * 16 + addr];
            s = fmaf(v, v, s);
        }
        x2arr[addr] = s;
    }
    __syncthreads();

    // ---- Phase A: 4b x 4k tile, b packed as f32x2 pairs ----
    // thread (c, r): b in {c, c+4, c+8, c+12} (pairs (c,c+4),(c+8,c+12)),
    //                k in {r, r+16, r+32, r+48}
    const int c = tid & 3;
    const int r = tid >> 2;

    ull acc2[2][4];
#pragma unroll
    for (int i = 0; i < 2; ++i)
#pragma unroll
        for (int j = 0; j < 4; ++j) acc2[i][j] = 0ULL;  // (0.f, 0.f)

#pragma unroll 4
    for (int d4 = 0; d4 < D4v; ++d4) {
        float4 tv[4];
#pragma unroll
        for (int j = 0; j < 4; ++j) tv[j] = ts[(r + 16 * j) * TP + d4];  // LDS.128
#pragma unroll
        for (int dd = 0; dd < 4; ++dd) {
            const float* xr = &xs2[(4 * d4 + dd) * 16];
            const ull xp0 = *reinterpret_cast<const ull*>(xr + 2 * c);       // LDS.64
            const ull xp1 = *reinterpret_cast<const ull*>(xr + 2 * c + 8);   // LDS.64
#pragma unroll
            for (int j = 0; j < 4; ++j) {
                const float tf = (dd == 0) ? tv[j].x : (dd == 1) ? tv[j].y
                               : (dd == 2) ? tv[j].z : tv[j].w;
                const ull tt = f2_splat(tf);
                acc2[0][j] = f2_fma(xp0, tt, acc2[0][j]);
                acc2[1][j] = f2_fma(xp1, tt, acc2[1][j]);
            }
        }
    }

    // ---- distances: d = x2 + t2 - 2*xt (packed); keep regs + write ds ----
    const ull m2 = f2_splat(-2.0f);
    const ull x2p0 = *reinterpret_cast<const ull*>(&x2arr[2 * c]);
    const ull x2p1 = *reinterpret_cast<const ull*>(&x2arr[2 * c + 8]);
    float df[4][4];  // [m][j]: b = c + 4m, k = r + 16j
#pragma unroll
    for (int j = 0; j < 4; ++j) {
        const int k = r + 16 * j;
        const ull t22 = f2_splat(t2s[k]);
        const ull d0 = f2_fma(acc2[0][j], m2, f2_add(x2p0, t22));
        const ull d1 = f2_fma(acc2[1][j], m2, f2_add(x2p1, t22));
        // pair 0 halves -> m=0 (b=c), m=1 (b=c+4); pair 1 -> m=2, m=3
        f2_unpack(d0, df[0][j], df[1][j]);
        f2_unpack(d1, df[2][j], df[3][j]);
        ds[(c)      * 65 + k] = df[0][j];
        ds[(c + 4)  * 65 + k] = df[1][j];
        ds[(c + 8)  * 65 + k] = df[2][j];
        ds[(c + 12) * 65 + k] = df[3][j];
    }
    __syncthreads();

    // ---- min+argmin per b: 32 threads scan half the k range each ----
    if (tid < 32) {
        const int b = tid & 15;
        const int h = tid >> 4;
        const float* row = &ds[b * 65 + h * 32];
        float best = FLT_MAX;
        int   bk   = h * 32;
#pragma unroll
        for (int kk = 0; kk < 32; ++kk) {
            const float v = row[kk];
            if (v < best) { best = v; bk = h * 32 + kk; }  // strict < => first occurrence
        }
        pv[tid]  = best;
        pki[tid] = bk;
    }
    __syncthreads();
    if (tid < Bv) {
        float v0 = pv[tid];      int k0 = pki[tid];
        float v1 = pv[tid + 16]; int k1 = pki[tid + 16];
        if (v1 < v0) { v0 = v1; k0 = k1; }   // tie -> lower half (lower k)
        bestvs[tid] = v0;
        bestks[tid] = k0;
    }
    __syncthreads();

    // ---- near-tie candidate count per b ----
#pragma unroll
    for (int m = 0; m < 4; ++m) {
        const int b = c + 4 * m;
        const float lim = bestvs[b] + EPS;
        int local = 0;
#pragma unroll
        for (int j = 0; j < 4; ++j) local += (df[m][j] <= lim) ? 1 : 0;
        if (local) atomicAdd(&cnt[b], local);
    }
    __syncthreads();

    // ---- Phase B (RARE): exact fp64 refinement for contested b ----
#pragma unroll
    for (int m = 0; m < 4; ++m) {
        const int b = c + 4 * m;
        if (cnt[b] < 2) continue;                 // uncontested: skip fp64
        const float lim  = bestvs[b] + EPS;
        const int   addr = xslot_f(b) * 2 + xhalf_f(b);
#pragma unroll
        for (int j = 0; j < 4; ++j) {
            if (df[m][j] > lim) continue;
            const int k = r + 16 * j;
            double dd = 0.0;
            for (int d4 = 0; d4 < D4v; ++d4) {
                const float4 tv = ts[k * TP + d4];
                const float tvj[4] = {tv.x, tv.y, tv.z, tv.w};
                for (int q = 0; q < 4; ++q) {
                    const double e = (double)xs2[(4 * d4 + q) * 16 + addr] - (double)tvj[q];
                    dd = fma(e, e, dd);
                }
            }
            const float dfx = (float)dd;          // exact -> fp32
            const ull key = ((ull)__float_as_uint(dfx) << 6) | (ull)k;
            atomicMin(&refined[b], key);
        }
    }
    __syncthreads();

    // ---- outputs ----
    if (tid < Bv) {
        float bestv;
        int   bestk;
        if (cnt[tid] >= 2) {
            const ull key = refined[tid];
            bestk = (int)(key & 63ULL);
            bestv = __uint_as_float((unsigned int)(key >> 6));
        } else {
            bestv = bestvs[tid];
            bestk = bestks[tid];
        }
        const size_t BN = (size_t)Bv * Nv;
        const size_t o  = (size_t)tid * Nv + n;
        out[o]           = (bestv <= 0.5f) ? 1.0f : 0.0f;  // mask @ 0.5
        out[BN + o]      = (bestv <= 1.0f) ? 1.0f : 0.0f;  // mask @ 1.0
        out[2 * BN + o]  = bestv;                          // min_dists
        out[3 * BN + o]  = clsf[bestk];                    // pred_classes
    }
}

extern "C" void kernel_launch(void* const* d_in, const int* in_sizes, int n_in,
                              void* d_out, int out_size)
{
    const float4* frame = (const float4*)d_in[0];   // [16,16384,64] f32
    const float4* tmpl  = (const float4*)d_in[1];   // [64,16384,64] f32
    const int*    tcls  = (const int*)d_in[2];      // [64] int32
    float*        out   = (float*)d_out;

    osc_kernel<<<Nv, 64>>>(frame, tmpl, tcls, out);
}

// round 7
// speedup vs baseline: 1.1581x; 1.1579x over previous
#include <cuda_runtime.h>
#include <cstdint>
#include <cfloat>

// Problem constants (fixed by the dataset)
constexpr int Bv  = 16;      // batch
constexpr int Nv  = 16384;   // pixels
constexpr int Dv  = 64;      // embed dim
constexpr int Kv  = 64;      // templates
constexpr int D4v = Dv / 4;  // float4 chunks per vector (16)
constexpr int PPB = 2;       // pixels per block (one per warp-pair -> all 4 SMSPs)
constexpr float EPS = 1e-3f; // near-tie margin (>> fp32 dist error ~1e-5)

using ull = unsigned long long;

// XOR swizzle (conflict-free per 8-lane phase for all our access patterns),
// replaces pitch padding so two pixels fit in <48KB static smem.
__device__ __forceinline__ int tsw(int k, int d4) { return k * 16 + (d4 ^ (k & 7)); }
__device__ __forceinline__ int xsw(int b, int d4) { return b * 16 + (d4 ^ (b & 7)); }

__global__ __launch_bounds__(128)
void osc_kernel(const float4* __restrict__ xg,     // frame_embeddings [B,N,D] f32
                const float4* __restrict__ tg,     // templates        [K,N,D] f32
                const int*    __restrict__ tcls,   // template_classes [K] int32
                float* __restrict__ out)
{
    __shared__ __align__(16) float4 ts[PPB][Kv * 16];  // template tiles (swizzled)
    __shared__ __align__(16) float4 xs[PPB][Bv * 16];  // frame tiles (swizzled)
    __shared__ float t2s[PPB][Kv];
    __shared__ float x2s[PPB][Bv];
    __shared__ float clsf[Kv];
    __shared__ float rv[PPB][Bv][17];                  // pitch 17: conflict-free scan
    __shared__ int   ri[PPB][Bv][17];
    __shared__ float bestvs[PPB][Bv];
    __shared__ int   bestks[PPB][Bv];
    __shared__ int   cnt[PPB][Bv];
    __shared__ ull   refined[PPB][Bv];

    const int tid = threadIdx.x;
    const int p   = tid >> 6;            // pixel slot 0/1 (warps 0,1 | 2,3)
    const int q   = tid & 63;            // thread id within pixel
    const int n   = blockIdx.x * PPB + p;

    // ---- stage tiles (each pixel's 64 threads; coalesced 512B per warp) ----
#pragma unroll
    for (int i = 0; i < 16; ++i) {
        int idx = q + i * 64;            // 1024 float4
        int k   = idx >> 4;
        int d4  = idx & 15;
        ts[p][tsw(k, d4)] = tg[((size_t)k * Nv + n) * D4v + d4];
    }
#pragma unroll
    for (int i = 0; i < 4; ++i) {
        int idx = q + i * 64;            // 256 float4
        int b   = idx >> 4;
        int d4  = idx & 15;
        xs[p][xsw(b, d4)] = xg[((size_t)b * Nv + n) * D4v + d4];
    }
    if (tid < Kv) clsf[tid] = (float)tcls[tid];
    if (q < Bv) {
        cnt[p][q]     = 0;
        refined[p][q] = 0xFFFFFFFFFFFFFFFFULL;
    }
    __syncthreads();

    // ---- norms: ||t_k||^2 (one row per thread), ||x_b||^2 (q<16) ----
    {
        float s0 = 0.f, s1 = 0.f, s2 = 0.f, s3 = 0.f;
#pragma unroll
        for (int d4 = 0; d4 < D4v; ++d4) {
            float4 v = ts[p][tsw(q, d4)];
            s0 = fmaf(v.x, v.x, s0); s1 = fmaf(v.y, v.y, s1);
            s2 = fmaf(v.z, v.z, s2); s3 = fmaf(v.w, v.w, s3);
        }
        t2s[p][q] = (s0 + s1) + (s2 + s3);
    }
    if (q < Bv) {
        float s0 = 0.f, s1 = 0.f, s2 = 0.f, s3 = 0.f;
#pragma unroll
        for (int d4 = 0; d4 < D4v; ++d4) {
            float4 v = xs[p][xsw(q, d4)];
            s0 = fmaf(v.x, v.x, s0); s1 = fmaf(v.y, v.y, s1);
            s2 = fmaf(v.z, v.z, s2); s3 = fmaf(v.w, v.w, s3);
        }
        x2s[p][q] = (s0 + s1) + (s2 + s3);
    }
    __syncthreads();

    // ---- Phase A: 4x4 register-tile fp32 dot products ----
    // thread covers b in {c, c+4, c+8, c+12}, k in {r, r+16, r+32, r+48}
    const int c = q & 3;
    const int r = q >> 2;

    float acc[4][4];
#pragma unroll
    for (int i = 0; i < 4; ++i)
#pragma unroll
        for (int j = 0; j < 4; ++j) acc[i][j] = 0.f;

#pragma unroll 4
    for (int d4 = 0; d4 < D4v; ++d4) {
        float4 xv[4], tv[4];
#pragma unroll
        for (int i = 0; i < 4; ++i) xv[i] = xs[p][xsw(c + 4 * i, d4)];
#pragma unroll
        for (int j = 0; j < 4; ++j) tv[j] = ts[p][tsw(r + 16 * j, d4)];
#pragma unroll
        for (int i = 0; i < 4; ++i)
#pragma unroll
            for (int j = 0; j < 4; ++j) {
                acc[i][j] = fmaf(xv[i].x, tv[j].x, acc[i][j]);
                acc[i][j] = fmaf(xv[i].y, tv[j].y, acc[i][j]);
                acc[i][j] = fmaf(xv[i].z, tv[j].z, acc[i][j]);
                acc[i][j] = fmaf(xv[i].w, tv[j].w, acc[i][j]);
            }
    }

    // distances in-place; per-thread min+argmin over its 4 k's per b
#pragma unroll
    for (int i = 0; i < 4; ++i) {
        const int   b   = c + 4 * i;
        const float bx2 = x2s[p][b];
        float bestv = FLT_MAX;
        int   bestk = Kv;
#pragma unroll
        for (int j = 0; j < 4; ++j) {
            const int k = r + 16 * j;
            const float d = bx2 + t2s[p][k] - 2.0f * acc[i][j];
            acc[i][j] = d;                            // keep for candidate pass
            if (d < bestv) { bestv = d; bestk = k; }  // j asc => first-min
        }
        rv[p][b][r] = bestv;
        ri[p][b][r] = bestk;
    }
    __syncthreads();

    // ---- fp32 min + argmin per b (q<16) ----
    if (q < Bv) {
        float bestv = rv[p][q][0];
        int   bestk = ri[p][q][0];
#pragma unroll
        for (int t = 1; t < 16; ++t) {
            const float v = rv[p][q][t];
            const int   k = ri[p][q][t];
            if (v < bestv || (v == bestv && k < bestk)) { bestv = v; bestk = k; }
        }
        bestvs[p][q] = bestv;
        bestks[p][q] = bestk;
    }
    __syncthreads();

    // ---- near-tie candidate count per b ----
#pragma unroll
    for (int i = 0; i < 4; ++i) {
        const int b = c + 4 * i;
        const float lim = bestvs[p][b] + EPS;
        int local = 0;
#pragma unroll
        for (int j = 0; j < 4; ++j) local += (acc[i][j] <= lim) ? 1 : 0;
        if (local) atomicAdd(&cnt[p][b], local);
    }
    __syncthreads();

    // ---- Phase B (RARE): exact fp64 refinement for contested b ----
#pragma unroll
    for (int i = 0; i < 4; ++i) {
        const int b = c + 4 * i;
        if (cnt[p][b] < 2) continue;                  // uncontested: skip fp64
        const float lim = bestvs[p][b] + EPS;
#pragma unroll
        for (int j = 0; j < 4; ++j) {
            if (acc[i][j] > lim) continue;
            const int k = r + 16 * j;
            double dd = 0.0;
            for (int d4 = 0; d4 < D4v; ++d4) {
                const float4 xv = xs[p][xsw(b, d4)];
                const float4 tv = ts[p][tsw(k, d4)];
                const double e0 = (double)xv.x - (double)tv.x;
                const double e1 = (double)xv.y - (double)tv.y;
                const double e2 = (double)xv.z - (double)tv.z;
                const double e3 = (double)xv.w - (double)tv.w;
                dd = fma(e0, e0, dd);
                dd = fma(e1, e1, dd);
                dd = fma(e2, e2, dd);
                dd = fma(e3, e3, dd);
            }
            const float dfx = (float)dd;              // exact -> fp32
            const ull key = ((ull)__float_as_uint(dfx) << 6) | (ull)k;
            atomicMin(&refined[p][b], key);
        }
    }
    __syncthreads();

    // ---- outputs ----
    if (q < Bv) {
        float bestv;
        int   bestk;
        if (cnt[p][q] >= 2) {
            const ull key = refined[p][q];
            bestk = (int)(key & 63ULL);
            bestv = __uint_as_float((unsigned int)(key >> 6));
        } else {
            bestv = bestvs[p][q];
            bestk = bestks[p][q];
        }
        const size_t BN = (size_t)Bv * Nv;
        const size_t o  = (size_t)q * Nv + n;
        out[o]           = (bestv <= 0.5f) ? 1.0f : 0.0f;  // mask @ 0.5
        out[BN + o]      = (bestv <= 1.0f) ? 1.0f : 0.0f;  // mask @ 1.0
        out[2 * BN + o]  = bestv;                          // min_dists
        out[3 * BN + o]  = clsf[bestk];                    // pred_classes
    }
}

extern "C" void kernel_launch(void* const* d_in, const int* in_sizes, int n_in,
                              void* d_out, int out_size)
{
    const float4* frame = (const float4*)d_in[0];   // [16,16384,64] f32
    const float4* tmpl  = (const float4*)d_in[1];   // [64,16384,64] f32
    const int*    tcls  = (const int*)d_in[2];      // [64] int32
    float*        out   = (float*)d_out;

    osc_kernel<<<Nv / PPB, 64 * PPB>>>(frame, tmpl, tcls, out);
}